// round 9
// baseline (speedup 1.0000x reference)
#include <cuda_runtime.h>
#include <cuda_bf16.h>
#include <stdint.h>

// Fused gather-concat:
//   out[r, 0:8]  = proc_pos[process_ids[r], :]   (16x8 f32 -> smem, transposed)
//   out[r, 8:11] = locs_sp[location_ids[r], :]   (500000x3 f32 -> padded float4 table)
//
// R8 finding: L1 wavefront throughput is the binder (77 wf/warp model matches
// 71.8%). R9: 2 rows per thread (t and t+256) -> 2 independent gathers + id
// loads in flight per thread (2x MLP), half the blocks/syncs. STS stays
// stride-11 conflict-free; flush stays fully-coalesced float4 (__stcs);
// ids read-once (__ldcs).

#define THREADS 256
#define ROWS_PER_THREAD 2
#define ROWS_PER_BLOCK (THREADS * ROWS_PER_THREAD)   // 512
#define PROC_DIM 8
#define SP_DIM 3
#define OUT_DIM 11
#define MAX_LOCS 500000

__device__ int g_ids_are_i64;
__device__ float4 g_locs_pad[MAX_LOCS];   // 8 MB static scratch

// Pad [num_locs,3] -> float4 table; block 0 also detects the id dtype.
__global__ __launch_bounds__(256)
void setup_kernel(const float* __restrict__ locs_sp, int num_locs,
                  const int* __restrict__ loc_ids_w, int naug)
{
    int i = blockIdx.x * blockDim.x + threadIdx.x;
    if (i < num_locs) {
        const float* s = locs_sp + (size_t)i * SP_DIM;
        float4 v;
        v.x = s[0]; v.y = s[1]; v.z = s[2]; v.w = 0.0f;
        g_locs_pad[i] = v;
    }

    // int64 little-endian ids with values < 5e5 look like (v,0,v,0,...):
    // every odd 32-bit word is zero. Random int32: P(64 zeros) ~ 0.
    if (blockIdx.x == 0) {
        __shared__ int s_not64;
        if (threadIdx.x == 0) s_not64 = 0;
        __syncthreads();
        int n_check = naug < 64 ? naug : 64;
        if (threadIdx.x < n_check) {
            if (loc_ids_w[2 * threadIdx.x + 1] != 0) atomicOr(&s_not64, 1);
        }
        __syncthreads();
        if (threadIdx.x == 0) g_ids_are_i64 = s_not64 ? 0 : 1;
    }
}

__global__ __launch_bounds__(THREADS)
void gather_concat_kernel(
    const float* __restrict__ proc_pos,   // [num_procs, 8]
    const float* __restrict__ locs_sp,    // [num_locs, 3] (fallback path only)
    const void*  __restrict__ process_ids,
    const void*  __restrict__ location_ids,
    float* __restrict__ out,              // [naug, 11]
    int naug,
    int num_procs,
    int num_locs,
    int use_padded)
{
    __shared__ float s_procT[PROC_DIM * 64];              // transposed [c][pid]
    __shared__ float s_stage[ROWS_PER_BLOCK * OUT_DIM];   // 22528 B

    const int tid = threadIdx.x;

    const int proc_elems = num_procs * PROC_DIM;
    for (int i = tid; i < proc_elems; i += THREADS) {
        const int pid = i / PROC_DIM;
        const int c   = i % PROC_DIM;
        s_procT[c * num_procs + pid] = proc_pos[i];
    }
    __syncthreads();

    const long long base = (long long)blockIdx.x * ROWS_PER_BLOCK;
    const int ids64 = g_ids_are_i64;          // uniform across grid

    // Two rows per thread: slots tid and tid+256 (keeps STS conflict-free
    // and id loads warp-coalesced, while giving 2x independent MLP).
    #pragma unroll
    for (int sub = 0; sub < ROWS_PER_THREAD; sub++) {
        const int slot = tid + sub * THREADS;
        const int row = (int)base + slot;
        if (row < naug) {
            int pid, lid;
            if (ids64) {
                pid = (int)__ldcs(&((const long long*)process_ids)[row]);
                lid = (int)__ldcs(&((const long long*)location_ids)[row]);
            } else {
                pid = __ldcs(&((const int*)process_ids)[row]);
                lid = __ldcs(&((const int*)location_ids)[row]);
            }
            pid = min(max(pid, 0), num_procs - 1);
            lid = min(max(lid, 0), num_locs - 1);

            float* dst = &s_stage[slot * OUT_DIM];

            // Location gather first: get the long-latency load in flight.
            if (use_padded) {
                float4 v = __ldcg(&g_locs_pad[lid]);
                // Conflict-free proc gather from transposed smem table.
                #pragma unroll
                for (int c = 0; c < PROC_DIM; c++)
                    dst[c] = s_procT[c * num_procs + pid];
                dst[PROC_DIM + 0] = v.x;
                dst[PROC_DIM + 1] = v.y;
                dst[PROC_DIM + 2] = v.z;
            } else {
                float a = __ldcg(&locs_sp[(size_t)lid * SP_DIM + 0]);
                float b = __ldcg(&locs_sp[(size_t)lid * SP_DIM + 1]);
                float d = __ldcg(&locs_sp[(size_t)lid * SP_DIM + 2]);
                #pragma unroll
                for (int c = 0; c < PROC_DIM; c++)
                    dst[c] = s_procT[c * num_procs + pid];
                dst[PROC_DIM + 0] = a;
                dst[PROC_DIM + 1] = b;
                dst[PROC_DIM + 2] = d;
            }
        }
    }
    __syncthreads();

    if (base + ROWS_PER_BLOCK <= (long long)naug) {
        // Full block: 1408 float4 coalesced streaming stores.
        const float4* s4 = (const float4*)s_stage;
        float4* o4 = (float4*)(out + (size_t)base * OUT_DIM);
        #pragma unroll
        for (int i = tid; i < (ROWS_PER_BLOCK * OUT_DIM) / 4; i += THREADS)
            __stcs(&o4[i], s4[i]);
    } else {
        // Tail block (not hit when naug % 512 == 0): scalar flush.
        const int nrows = naug - (int)base;
        if (nrows > 0) {
            const int total = nrows * OUT_DIM;
            float* o = out + (size_t)base * OUT_DIM;
            for (int i = tid; i < total; i += THREADS)
                o[i] = s_stage[i];
        }
    }
}

extern "C" void kernel_launch(void* const* d_in, const int* in_sizes, int n_in,
                              void* d_out, int out_size) {
    const float* proc_pos     = (const float*)d_in[0];
    const float* locs_sp      = (const float*)d_in[1];
    const void*  process_ids  = d_in[2];
    const void*  location_ids = d_in[3];
    float* out = (float*)d_out;

    const int naug      = in_sizes[2];              // 8,000,000
    const int num_procs = in_sizes[0] / PROC_DIM;   // 16
    const int num_locs  = in_sizes[1] / SP_DIM;     // 500,000
    const int use_padded = (num_locs <= MAX_LOCS) ? 1 : 0;

    {
        const int work = use_padded ? num_locs : 256;
        const int pg = (work + 255) / 256;
        setup_kernel<<<pg, 256>>>(locs_sp, use_padded ? num_locs : 0,
                                  (const int*)location_ids, naug);
    }

    const int grid = (naug + ROWS_PER_BLOCK - 1) / ROWS_PER_BLOCK;
    gather_concat_kernel<<<grid, THREADS>>>(
        proc_pos, locs_sp, process_ids, location_ids, out,
        naug, num_procs, num_locs, use_padded);
}

// round 10
// speedup vs baseline: 1.2098x; 1.2098x over previous
#include <cuda_runtime.h>
#include <cuda_bf16.h>
#include <stdint.h>

// Fused gather-concat:
//   out[r, 0:8]  = proc_pos[process_ids[r], :]   (16x8 f32 -> smem, transposed)
//   out[r, 8:11] = locs_sp[location_ids[r], :]   (500000x3 f32 -> padded float4 table)
//
// R9 (2 rows/thread) regressed: barrier waited on max of 512 gathers and
// front-batched LDGs raised cross-CTA L1tex-queue spread. R10: back to 1
// row/thread, but staging is WARP-PRIVATE (32 rows x 11 f32 = 1408 B/warp),
// so __syncwarp replaces __syncthreads -- warps progress independently, no
// block-wide barrier tail. STS lane-stride 11 (odd) = conflict-free; flush is
// 88 contiguous float4/warp (16B-aligned), fully coalesced __stcs.

#define THREADS 256
#define WARPS (THREADS / 32)
#define PROC_DIM 8
#define SP_DIM 3
#define OUT_DIM 11
#define MAX_LOCS 500000

__device__ int g_ids_are_i64;
__device__ float4 g_locs_pad[MAX_LOCS];   // 8 MB static scratch

// Pad [num_locs,3] -> float4 table; block 0 also detects the id dtype.
__global__ __launch_bounds__(256)
void setup_kernel(const float* __restrict__ locs_sp, int num_locs,
                  const int* __restrict__ loc_ids_w, int naug)
{
    int i = blockIdx.x * blockDim.x + threadIdx.x;
    if (i < num_locs) {
        const float* s = locs_sp + (size_t)i * SP_DIM;
        float4 v;
        v.x = s[0]; v.y = s[1]; v.z = s[2]; v.w = 0.0f;
        g_locs_pad[i] = v;
    }

    // int64 little-endian ids with values < 5e5 look like (v,0,v,0,...):
    // every odd 32-bit word is zero. Random int32: P(64 zeros) ~ 0.
    if (blockIdx.x == 0) {
        __shared__ int s_not64;
        if (threadIdx.x == 0) s_not64 = 0;
        __syncthreads();
        int n_check = naug < 64 ? naug : 64;
        if (threadIdx.x < n_check) {
            if (loc_ids_w[2 * threadIdx.x + 1] != 0) atomicOr(&s_not64, 1);
        }
        __syncthreads();
        if (threadIdx.x == 0) g_ids_are_i64 = s_not64 ? 0 : 1;
    }
}

__global__ __launch_bounds__(THREADS)
void gather_concat_kernel(
    const float* __restrict__ proc_pos,   // [num_procs, 8]
    const float* __restrict__ locs_sp,    // [num_locs, 3] (fallback path only)
    const void*  __restrict__ process_ids,
    const void*  __restrict__ location_ids,
    float* __restrict__ out,              // [naug, 11]
    int naug,
    int num_procs,
    int num_locs,
    int use_padded)
{
    __shared__ float s_procT[PROC_DIM * 64];          // transposed [c][pid]
    __shared__ float s_stage[THREADS * OUT_DIM];      // 11264 B, per-warp segments

    const int tid  = threadIdx.x;
    const int warp = tid >> 5;
    const int lane = tid & 31;

    const int proc_elems = num_procs * PROC_DIM;
    for (int i = tid; i < proc_elems; i += THREADS) {
        const int pid = i / PROC_DIM;
        const int c   = i % PROC_DIM;
        s_procT[c * num_procs + pid] = proc_pos[i];
    }
    __syncthreads();   // once per block: proc table ready

    const long long base = (long long)blockIdx.x * THREADS;
    const int row = (int)base + tid;          // naug = 8e6 fits int32
    const int ids64 = g_ids_are_i64;          // uniform across grid

    float* wstage = &s_stage[warp * 32 * OUT_DIM];   // 1408 B per warp

    if (row < naug) {
        int pid, lid;
        if (ids64) {
            pid = (int)__ldcs(&((const long long*)process_ids)[row]);
            lid = (int)__ldcs(&((const long long*)location_ids)[row]);
        } else {
            pid = __ldcs(&((const int*)process_ids)[row]);
            lid = __ldcs(&((const int*)location_ids)[row]);
        }
        pid = min(max(pid, 0), num_procs - 1);
        lid = min(max(lid, 0), num_locs - 1);

        float* dst = &wstage[lane * OUT_DIM];

        if (use_padded) {
            float4 v = __ldcg(&g_locs_pad[lid]);
            #pragma unroll
            for (int c = 0; c < PROC_DIM; c++)
                dst[c] = s_procT[c * num_procs + pid];
            dst[PROC_DIM + 0] = v.x;
            dst[PROC_DIM + 1] = v.y;
            dst[PROC_DIM + 2] = v.z;
        } else {
            float a = __ldcg(&locs_sp[(size_t)lid * SP_DIM + 0]);
            float b = __ldcg(&locs_sp[(size_t)lid * SP_DIM + 1]);
            float d = __ldcg(&locs_sp[(size_t)lid * SP_DIM + 2]);
            #pragma unroll
            for (int c = 0; c < PROC_DIM; c++)
                dst[c] = s_procT[c * num_procs + pid];
            dst[PROC_DIM + 0] = a;
            dst[PROC_DIM + 1] = b;
            dst[PROC_DIM + 2] = d;
        }
    }
    __syncwarp();   // warp-local: stage visible to flushing lanes

    const long long wbase = base + warp * 32;   // first row of this warp
    if (wbase + 32 <= (long long)naug) {
        // Full warp: 88 contiguous float4 stores (1408 B, 16B-aligned).
        const float4* s4 = (const float4*)wstage;
        float4* o4 = (float4*)(out + (size_t)wbase * OUT_DIM);
        #pragma unroll
        for (int i = lane; i < (32 * OUT_DIM) / 4; i += 32)
            __stcs(&o4[i], s4[i]);
    } else if (wbase < (long long)naug) {
        // Tail warp (not hit when naug % 256 == 0): scalar flush.
        const int nrows = naug - (int)wbase;
        const int total = nrows * OUT_DIM;
        float* o = out + (size_t)wbase * OUT_DIM;
        for (int i = lane; i < total; i += 32)
            o[i] = wstage[i];
    }
}

extern "C" void kernel_launch(void* const* d_in, const int* in_sizes, int n_in,
                              void* d_out, int out_size) {
    const float* proc_pos     = (const float*)d_in[0];
    const float* locs_sp      = (const float*)d_in[1];
    const void*  process_ids  = d_in[2];
    const void*  location_ids = d_in[3];
    float* out = (float*)d_out;

    const int naug      = in_sizes[2];              // 8,000,000
    const int num_procs = in_sizes[0] / PROC_DIM;   // 16
    const int num_locs  = in_sizes[1] / SP_DIM;     // 500,000
    const int use_padded = (num_locs <= MAX_LOCS) ? 1 : 0;

    {
        const int work = use_padded ? num_locs : 256;
        const int pg = (work + 255) / 256;
        setup_kernel<<<pg, 256>>>(locs_sp, use_padded ? num_locs : 0,
                                  (const int*)location_ids, naug);
    }

    const int grid = (naug + THREADS - 1) / THREADS;
    gather_concat_kernel<<<grid, THREADS>>>(
        proc_pos, locs_sp, process_ids, location_ids, out,
        naug, num_procs, num_locs, use_padded);
}

// round 11
// speedup vs baseline: 1.2747x; 1.0536x over previous
#include <cuda_runtime.h>
#include <cuda_bf16.h>
#include <stdint.h>

// Fused gather-concat:
//   out[r, 0:8]  = proc_pos[process_ids[r], :]   (16x8 f32 -> smem, transposed)
//   out[r, 8:11] = locs_sp[location_ids[r], :]   (500000x3 f32 -> padded float4 table)
//
// R11: persistent warps + software pipeline. Each warp grid-strides over
// 32-row tiles; the NEXT tile's id loads are issued one full iteration ahead,
// so the ~600cyc DRAM id latency is fully hidden; only the L2 gather wait is
// exposed (covered by co-resident warps). Warp-private staging (1408 B/warp,
// lane-stride-11 STS = conflict-free), flush = 88 contiguous float4 __stcs.

#define THREADS 256
#define WARPS (THREADS / 32)
#define PROC_DIM 8
#define SP_DIM 3
#define OUT_DIM 11
#define MAX_LOCS 500000
#define TILE 32

__device__ int g_ids_are_i64;
__device__ float4 g_locs_pad[MAX_LOCS];   // 8 MB static scratch

// Pad [num_locs,3] -> float4 table; block 0 also detects the id dtype.
__global__ __launch_bounds__(256)
void setup_kernel(const float* __restrict__ locs_sp, int num_locs,
                  const int* __restrict__ loc_ids_w, int naug)
{
    int i = blockIdx.x * blockDim.x + threadIdx.x;
    if (i < num_locs) {
        const float* s = locs_sp + (size_t)i * SP_DIM;
        float4 v;
        v.x = s[0]; v.y = s[1]; v.z = s[2]; v.w = 0.0f;
        g_locs_pad[i] = v;
    }

    // int64 little-endian ids with values < 5e5 look like (v,0,v,0,...):
    // every odd 32-bit word is zero. Random int32: P(64 zeros) ~ 0.
    if (blockIdx.x == 0) {
        __shared__ int s_not64;
        if (threadIdx.x == 0) s_not64 = 0;
        __syncthreads();
        int n_check = naug < 64 ? naug : 64;
        if (threadIdx.x < n_check) {
            if (loc_ids_w[2 * threadIdx.x + 1] != 0) atomicOr(&s_not64, 1);
        }
        __syncthreads();
        if (threadIdx.x == 0) g_ids_are_i64 = s_not64 ? 0 : 1;
    }
}

__device__ __forceinline__ void load_ids(
    const void* process_ids, const void* location_ids,
    int row, int naug, int ids64, long long& rp, long long& rl)
{
    if (row < naug) {
        if (ids64) {
            rp = __ldcs(&((const long long*)process_ids)[row]);
            rl = __ldcs(&((const long long*)location_ids)[row]);
        } else {
            rp = (long long)__ldcs(&((const int*)process_ids)[row]);
            rl = (long long)__ldcs(&((const int*)location_ids)[row]);
        }
    } else {
        rp = 0; rl = 0;
    }
}

__global__ __launch_bounds__(THREADS)
void gather_concat_kernel(
    const float* __restrict__ proc_pos,   // [num_procs, 8]
    const float* __restrict__ locs_sp,    // [num_locs, 3] (unused fast path)
    const void*  __restrict__ process_ids,
    const void*  __restrict__ location_ids,
    float* __restrict__ out,              // [naug, 11]
    int naug,
    int num_procs,
    int num_locs,
    long long ntiles)
{
    __shared__ float s_procT[PROC_DIM * 64];          // transposed [c][pid]
    __shared__ float s_stage[THREADS * OUT_DIM];      // 11264 B, per-warp segments

    const int tid  = threadIdx.x;
    const int warp = tid >> 5;
    const int lane = tid & 31;

    const int proc_elems = num_procs * PROC_DIM;
    for (int i = tid; i < proc_elems; i += THREADS) {
        const int pid = i / PROC_DIM;
        const int c   = i % PROC_DIM;
        s_procT[c * num_procs + pid] = proc_pos[i];
    }
    __syncthreads();   // proc table ready (only block-wide sync)

    const int ids64 = g_ids_are_i64;   // uniform
    float* wstage = &s_stage[warp * TILE * OUT_DIM];   // 1408 B per warp

    const long long gw = (long long)blockIdx.x * WARPS + warp;   // global warp id
    const long long GW = (long long)gridDim.x * WARPS;           // warp stride

    long long t = gw;
    long long rp, rl;
    if (t < ntiles)
        load_ids(process_ids, location_ids, (int)(t * TILE) + lane, naug, ids64, rp, rl);

    while (t < ntiles) {
        const long long tn = t + GW;

        // Indices for current tile (ids prefetched an iteration ago -> no stall).
        int pid = (int)rp, lid = (int)rl;
        pid = min(max(pid, 0), num_procs - 1);
        lid = min(max(lid, 0), num_locs - 1);

        // Issue the gather immediately.
        float4 v = __ldcg(&g_locs_pad[lid]);

        // Prefetch next tile's ids while the gather is in flight.
        long long rp_n = 0, rl_n = 0;
        if (tn < ntiles)
            load_ids(process_ids, location_ids, (int)(tn * TILE) + lane, naug, ids64, rp_n, rl_n);

        // Stage: proc part from smem table (conflict-free), loc part from v.
        const int rb = (int)(t * TILE);           // tile base row
        if (rb + lane < naug) {
            float* dst = &wstage[lane * OUT_DIM];
            #pragma unroll
            for (int c = 0; c < PROC_DIM; c++)
                dst[c] = s_procT[c * num_procs + pid];
            dst[PROC_DIM + 0] = v.x;
            dst[PROC_DIM + 1] = v.y;
            dst[PROC_DIM + 2] = v.z;
        }
        __syncwarp();

        // Flush this warp's 32 rows.
        if (rb + TILE <= naug) {
            const float4* s4 = (const float4*)wstage;
            float4* o4 = (float4*)(out + (size_t)rb * OUT_DIM);
            #pragma unroll
            for (int i = lane; i < (TILE * OUT_DIM) / 4; i += 32)
                __stcs(&o4[i], s4[i]);
        } else {
            const int nrows = naug - rb;
            const int total = nrows * OUT_DIM;
            float* o = out + (size_t)rb * OUT_DIM;
            for (int i = lane; i < total; i += 32)
                o[i] = wstage[i];
        }
        __syncwarp();   // protect stage buffer before next iteration's writes

        rp = rp_n; rl = rl_n;
        t = tn;
    }
}

extern "C" void kernel_launch(void* const* d_in, const int* in_sizes, int n_in,
                              void* d_out, int out_size) {
    const float* proc_pos     = (const float*)d_in[0];
    const float* locs_sp      = (const float*)d_in[1];
    const void*  process_ids  = d_in[2];
    const void*  location_ids = d_in[3];
    float* out = (float*)d_out;

    const int naug      = in_sizes[2];              // 8,000,000
    const int num_procs = in_sizes[0] / PROC_DIM;   // 16
    const int num_locs  = in_sizes[1] / SP_DIM;     // 500,000

    {
        const int pg = (num_locs + 255) / 256;
        setup_kernel<<<pg, 256>>>(locs_sp, num_locs,
                                  (const int*)location_ids, naug);
    }

    const long long ntiles = ((long long)naug + TILE - 1) / TILE;   // 250000
    // Persistent grid: ~8 blocks/SM on 148+ SMs; grid-stride covers all tiles.
    long long max_blocks = (ntiles + WARPS - 1) / WARPS;
    int grid = (int)(max_blocks < 1184 ? max_blocks : 1184);
    gather_concat_kernel<<<grid, THREADS>>>(
        proc_pos, locs_sp, process_ids, location_ids, out,
        naug, num_procs, num_locs, ntiles);
}